// round 15
// baseline (speedup 1.0000x reference)
#include <cuda_runtime.h>
#include <cuda_bf16.h>
#include <math.h>
#include <stdint.h>

#define V_ 8000
#define B_ 64
#define T_ 256
#define R_ 1024
#define U_ 512
#define S_ 1024
#define N_ (B_ * T_)

#define RCTA 128
#define RTHR 256

// ---------------------------------------------------------------------------
// Device global scratch
// ---------------------------------------------------------------------------
__device__ float g_Eh[(size_t)V_ * R_];
__device__ float g_Et[(size_t)V_ * R_];
__device__ float g_states[(size_t)T_ * B_ * R_];
__device__ uint32_t g_Wf[(size_t)3 * 128 * 16384];
__device__ uint32_t g_Sf[2 * 32768];
__device__ float g_outb[(size_t)N_ * U_];
__device__ float g_logits[(size_t)N_ * S_];
__device__ float g_sbv[S_];
__device__ float g_loss[N_];
__device__ unsigned int g_bar;
// B fragment buffers: [K/16][N/8][lane32] uint4{hi0,hi1,lo0,lo1}
__device__ uint4 g_Bf_eh[131072];
__device__ uint4 g_Bf_et[131072];
__device__ uint4 g_Bf_op[131072];
__device__ uint4 g_Bf_lg[131072];
// A fragment planes (bf16 hi only): [M/16][K/16][lane32] uint4
__device__ uint4 g_Aemb_h[512000];
__device__ uint4 g_Ast_h[2097152];
__device__ uint4 g_Aob_h[1048576];

// ---------------------------------------------------------------------------
// PTX helpers
// ---------------------------------------------------------------------------
__device__ __forceinline__ void mma_acc(float* d, const uint4& a, uint32_t b0, uint32_t b1) {
    asm volatile(
        "mma.sync.aligned.m16n8k16.row.col.f32.bf16.bf16.f32 "
        "{%0,%1,%2,%3},{%4,%5,%6,%7},{%8,%9},{%0,%1,%2,%3};"
        : "+f"(d[0]), "+f"(d[1]), "+f"(d[2]), "+f"(d[3])
        : "r"(a.x), "r"(a.y), "r"(a.z), "r"(a.w), "r"(b0), "r"(b1));
}
__device__ __forceinline__ uint4 ldg128cg(const uint4* p) {
    uint4 v;
    asm volatile("ld.global.cg.v4.u32 {%0,%1,%2,%3}, [%4];"
                 : "=r"(v.x), "=r"(v.y), "=r"(v.z), "=r"(v.w) : "l"(p));
    return v;
}
__device__ __forceinline__ void grid_sync(unsigned int target, unsigned int* bar) {
    __syncthreads();
    if (threadIdx.x == 0) {
        asm volatile("red.release.gpu.global.add.u32 [%0], 1;" :: "l"(bar) : "memory");
        unsigned int v;
        do {
            asm volatile("ld.acquire.gpu.global.u32 %0, [%1];" : "=r"(v) : "l"(bar) : "memory");
        } while (v < target);
    }
    __syncthreads();
}
__device__ __forceinline__ uint32_t pack_hi(float x0, float x1) {
    uint16_t h0 = __bfloat16_as_ushort(__float2bfloat16(x0));
    uint16_t h1 = __bfloat16_as_ushort(__float2bfloat16(x1));
    return ((uint32_t)h1 << 16) | h0;
}
__device__ __forceinline__ uint32_t pack_lo(float x0, float x1) {
    float r0 = x0 - __bfloat162float(__float2bfloat16(x0));
    float r1 = x1 - __bfloat162float(__float2bfloat16(x1));
    return pack_hi(r0, r1);
}
__device__ __forceinline__ float tanh_ap(float x) {
    float y;
    asm("tanh.approx.f32 %0, %1;" : "=f"(y) : "f"(x));
    return y;
}
__device__ __forceinline__ float sigm_ap(float x) {
    float e;
    asm("ex2.approx.f32 %0, %1;" : "=f"(e) : "f"(-x * 1.4426950408889634f));
    float r;
    asm("rcp.approx.f32 %0, %1;" : "=f"(r) : "f"(1.f + e));
    return r;
}

// ---------------------------------------------------------------------------
// Setup kernels
// ---------------------------------------------------------------------------
__global__ void init_kernel(uint32_t* sf) {
    int i = blockIdx.x * 256 + threadIdx.x;
    if (i == 0) g_bar = 0u;
    if (i < 2 * 32768) sf[i] = 0u;
}

__global__ void sb_kernel(const int* __restrict__ sampled,
                          const float* __restrict__ softmax_b,
                          const float* __restrict__ scounts,
                          float* __restrict__ sbv) {
    int j = blockIdx.x * 256 + threadIdx.x;
    if (j < S_) sbv[j] = softmax_b[sampled[j]] - logf(scounts[j]);
}

// B-fragment prep from row-major src[k][n]
__global__ __launch_bounds__(256)
void prep_b_kn(const float* __restrict__ src, uint4* __restrict__ out,
               int K, int N, int ldb) {
    int idx = blockIdx.x * 256 + threadIdx.x;
    int total = (K >> 4) * (N >> 3) * 32;
    if (idx >= total) return;
    int lane = idx & 31;
    int nt = (idx >> 5) % (N >> 3);
    int gks = (idx >> 5) / (N >> 3);
    int g = lane >> 2, tg = lane & 3;
    int n = nt * 8 + g;
    int k0 = gks * 16 + tg * 2;
    float a0 = src[(size_t)k0 * ldb + n];
    float a1 = src[(size_t)(k0 + 1) * ldb + n];
    float a2 = src[(size_t)(k0 + 8) * ldb + n];
    float a3 = src[(size_t)(k0 + 9) * ldb + n];
    out[idx] = make_uint4(pack_hi(a0, a1), pack_hi(a2, a3),
                          pack_lo(a0, a1), pack_lo(a2, a3));
}

__global__ __launch_bounds__(256)
void prep_b_gather(const float* __restrict__ sw, const int* __restrict__ sampled,
                   uint4* __restrict__ out) {
    int idx = blockIdx.x * 256 + threadIdx.x;
    const int K = U_, N = S_;
    int total = (K >> 4) * (N >> 3) * 32;
    if (idx >= total) return;
    int lane = idx & 31;
    int nt = (idx >> 5) % (N >> 3);
    int gks = (idx >> 5) / (N >> 3);
    int g = lane >> 2, tg = lane & 3;
    int n = nt * 8 + g;
    int k0 = gks * 16 + tg * 2;
    const float* row = sw + (size_t)sampled[n] * U_;
    float a0 = row[k0], a1 = row[k0 + 1], a2 = row[k0 + 8], a3 = row[k0 + 9];
    out[idx] = make_uint4(pack_hi(a0, a1), pack_hi(a2, a3),
                          pack_lo(a0, a1), pack_lo(a2, a3));
}

// A-fragment prep (hi plane only). REMAP 1: row = (row%T)*B + row/T
template <int REMAP>
__global__ __launch_bounds__(256)
void prep_a(const float* __restrict__ src, uint4* __restrict__ hi,
            int M, int K, int lda) {
    int idx = blockIdx.x * 256 + threadIdx.x;
    int total = (M >> 4) * (K >> 4) * 32;
    if (idx >= total) return;
    int lane = idx & 31;
    int kt = (idx >> 5) % (K >> 4);
    int mt = (idx >> 5) / (K >> 4);
    int r = lane >> 2;
    int k0 = kt * 16 + (lane & 3) * 2;
    int row0 = mt * 16 + r, row1 = row0 + 8;
    const float *p0, *p1;
    if (REMAP) {
        p0 = src + (size_t)((row0 % T_) * B_ + row0 / T_) * lda;
        p1 = src + (size_t)((row1 % T_) * B_ + row1 / T_) * lda;
    } else {
        p0 = src + (size_t)row0 * lda;
        p1 = src + (size_t)row1 * lda;
    }
    float2 v0 = *(const float2*)(p0 + k0);
    float2 v1 = *(const float2*)(p1 + k0);
    float2 v2 = *(const float2*)(p0 + k0 + 8);
    float2 v3 = *(const float2*)(p1 + k0 + 8);
    hi[idx] = make_uint4(pack_hi(v0.x, v0.y), pack_hi(v1.x, v1.y),
                         pack_hi(v2.x, v2.y), pack_hi(v3.x, v3.y));
}

// Weight -> fragment-linear bf16 hi/lo for recurrence.
__global__ __launch_bounds__(256)
void wcvt_kernel(const float* __restrict__ Wh0, const float* __restrict__ Wt0,
                 const float* __restrict__ Wh,  const float* __restrict__ Wt,
                 uint32_t* __restrict__ Wf) {
    __shared__ float ws[256][17];
    int b = blockIdx.x;
    int cta = b & 127;
    int l = b >> 7;
    int cbase = cta * 8;
    int tid = threadIdx.x;
    uint32_t* outp = Wf + (size_t)(l * 128 + cta) * 16384;

    for (int kb = 0; kb < 4; kb++) {
#pragma unroll
        for (int e = 0; e < 16; e++) {
            int idx = tid + e * 256;
            int k = idx >> 4, cg = idx & 15;
            int g = cg >> 3, c = cg & 7;
            int kg = kb * 256 + k;
            float v;
            if (l == 0) v = (g ? Wt0 : Wh0)[(size_t)(U_ + kg) * R_ + cbase + c];
            else        v = (g ? Wt : Wh)[((size_t)(l - 1) * R_ + kg) * R_ + cbase + c];
            ws[k][g * 8 + c] = v;
        }
        __syncthreads();
#pragma unroll
        for (int e = 0; e < 16; e++) {
            int o = tid + e * 256;
            int ksl = o >> 8;
            int rem = o & 255;
            int term = rem >> 7;
            int rem2 = rem & 127;
            int lane = rem2 >> 2;
            int r = rem2 & 3;
            int gate = r & 1;
            int c = lane >> 2;
            int kk = (lane & 3) * 2 + (r >> 1) * 8;
            int kl = ksl * 16 + kk;
            float w0 = ws[kl][gate * 8 + c];
            float w1 = ws[kl + 1][gate * 8 + c];
            uint32_t val = term ? pack_lo(w0, w1) : pack_hi(w0, w1);
            int ks = kb * 16 + ksl;
            outp[((ks * 2 + term) * 32 + lane) * 4 + r] = val;
        }
        __syncthreads();
    }
}

// ---------------------------------------------------------------------------
// Fragment tensor GEMM (2-term: Ahi*(Bhi+Blo)). No smem, no syncs.
// ---------------------------------------------------------------------------
template <int EMITC>
__global__ __launch_bounds__(256)
void tgemm_f(const uint4* __restrict__ Ah, const uint4* __restrict__ Bf,
             const float* __restrict__ bias, float* __restrict__ C,
             uint4* __restrict__ Ch, int M, int N, int K, int ldc) {
    const int tid = threadIdx.x;
    const int lane = tid & 31;
    const int w = tid >> 5;
    const int mh = w >> 2;
    const int nq = w & 3;
    const int bm = blockIdx.y * 64;
    const int bn = blockIdx.x * 64;
    const int KT = K >> 4, NT = N >> 3;

    const int mt0 = (bm >> 4) + mh * 2;
    const uint4* A0h = Ah + ((size_t)mt0 * KT) * 32 + lane;
    const uint4* A1h = A0h + (size_t)KT * 32;
    const uint4* Bp0 = Bf + ((size_t)(bn >> 3) + nq * 2) * 32 + lane;

    float d[2][2][4];
#pragma unroll
    for (int i = 0; i < 2; i++)
#pragma unroll
        for (int j = 0; j < 2; j++)
#pragma unroll
            for (int q = 0; q < 4; q++) d[i][j][q] = 0.f;

#pragma unroll 4
    for (int kt = 0; kt < KT; kt++) {
        uint4 aH0 = __ldg(A0h + kt * 32);
        uint4 aH1 = __ldg(A1h + kt * 32);
        uint4 b0 = ldg128cg(Bp0 + (size_t)kt * NT * 32);
        uint4 b1 = ldg128cg(Bp0 + (size_t)kt * NT * 32 + 32);
        mma_acc(d[0][0], aH0, b0.x, b0.y);
        mma_acc(d[0][0], aH0, b0.z, b0.w);
        mma_acc(d[0][1], aH0, b1.x, b1.y);
        mma_acc(d[0][1], aH0, b1.z, b1.w);
        mma_acc(d[1][0], aH1, b0.x, b0.y);
        mma_acc(d[1][0], aH1, b0.z, b0.w);
        mma_acc(d[1][1], aH1, b1.x, b1.y);
        mma_acc(d[1][1], aH1, b1.z, b1.w);
    }

    const int g = lane >> 2, tg = lane & 3;
#pragma unroll
    for (int mti = 0; mti < 2; mti++) {
        int row0 = bm + (mh * 2 + mti) * 16 + g;
        float v[2][4];
#pragma unroll
        for (int nti = 0; nti < 2; nti++) {
            int col = bn + nq * 16 + nti * 8 + tg * 2;
            float b0v = bias ? bias[col] : 0.f;
            float b1v = bias ? bias[col + 1] : 0.f;
            v[nti][0] = d[mti][nti][0] + b0v;
            v[nti][1] = d[mti][nti][1] + b1v;
            v[nti][2] = d[mti][nti][2] + b0v;
            v[nti][3] = d[mti][nti][3] + b1v;
            C[(size_t)row0 * ldc + col]           = v[nti][0];
            C[(size_t)row0 * ldc + col + 1]       = v[nti][1];
            C[(size_t)(row0 + 8) * ldc + col]     = v[nti][2];
            C[(size_t)(row0 + 8) * ldc + col + 1] = v[nti][3];
        }
        if (EMITC) {
            int KT2 = N >> 4;
            int mtile = (bm >> 4) + mh * 2 + mti;
            int ktile = (bn >> 4) + nq;
            size_t fi = ((size_t)mtile * KT2 + ktile) * 32 + lane;
            Ch[fi] = make_uint4(pack_hi(v[0][0], v[0][1]), pack_hi(v[0][2], v[0][3]),
                                pack_hi(v[1][0], v[1][1]), pack_hi(v[1][2], v[1][3]));
        }
    }
}

// ---------------------------------------------------------------------------
// Persistent recurrence: batch-split warps, full-K per warp, register epilogue.
// 8 warps x 8 batch cols; no cross-warp reduction, no compute-path syncthreads.
// ---------------------------------------------------------------------------
__global__ __launch_bounds__(RTHR, 1)
void rec_mma_kernel(const uint32_t* __restrict__ Wf,
                    uint32_t* __restrict__ Sf,
                    const int* __restrict__ input_data,
                    const float* __restrict__ Eh, const float* __restrict__ Et,
                    const float* __restrict__ bh, const float* __restrict__ bt,
                    float* __restrict__ states) {
    __shared__ float stage_st[64][8];   // 16B-aligned rows (float4 copy-out)

    const int tid = threadIdx.x;
    const int lane = tid & 31;
    const int w = tid >> 5;            // warp = batch group (8 cols)
    const int cta = blockIdx.x;
    const int cbase = cta * 8;
    const int g = lane >> 2;           // column within CTA's 8
    const int bq = lane & 3;
    const int b0 = w * 8 + bq * 2;     // this thread's two batch rows
    const int b1 = b0 + 1;
    const int col = cbase + g;
    const int gphalf = w >> 1;         // uint4 slot in S fragments
    const int sel = w & 1;             // which half of the uint4

    // biases in registers
    const float bh1v = bh[col], bt1v = bt[col];
    const float bh2v = bh[R_ + col], bt2v = bt[R_ + col];

    // persistent state registers for (col, b0) and (col, b1)
    float sold0 = 0.f, sold1 = 0.f;

    // Eh/Et prefetch for t=0
    float peh0, pet0, peh1, pet1;
    {
        int v0 = __ldg(&input_data[b0 * T_ + 0]);
        int v1 = __ldg(&input_data[b1 * T_ + 0]);
        peh0 = __ldg(&Eh[(size_t)v0 * R_ + col]);
        pet0 = __ldg(&Et[(size_t)v0 * R_ + col]);
        peh1 = __ldg(&Eh[(size_t)v1 * R_ + col]);
        pet1 = __ldg(&Et[(size_t)v1 * R_ + col]);
    }

    // precompute state-scatter index (same fragment layout as before)
    const int ec0 = g & ~1;
    const int kk0 = (cta & 1) * 8 + ec0;
    const int q = (kk0 >> 1) & 3;
    const int reg = cta & 1;
    const int bsel = (g & 1) ? b1 : b0;  // which batch row this thread's word covers
    const int gg = bsel >> 3;
    const int lt = (bsel & 7) * 4 + q;
    const int ksx = cta >> 1;
    const int slot = (gg & 1) * 2 + reg;
    const int gp2 = gg >> 1;
    const uint32_t sidx = (uint32_t)(((ksx * 4 + gp2) * 32 + lt) * 4 + slot);

    unsigned int pc = 0;
    int t = 0, l = 0;

    for (int p = 0; p < 3 * T_; p++) {
        // deferred fp32 states write for t-1 (overlaps this phase's loads)
        if (l == 0 && t > 0 && tid < 128) {
            int rb = tid >> 1, half = tid & 1;
            *(float4*)&states[((size_t)(t - 1) * B_ + rb) * R_ + cbase + half * 4] =
                *(float4*)&stage_st[rb][half * 4];
        }

        const int rbuf = p & 1;
        const uint4* SB = (const uint4*)(Sf + rbuf * 32768);
        uint32_t* sOut = Sf + (rbuf ^ 1) * 32768;
        const uint4* WA = (const uint4*)Wf + (size_t)(l * 128 + cta) * 4096;

        float dH[4][4], dL[4][4];
#pragma unroll
        for (int c = 0; c < 4; c++)
#pragma unroll
            for (int q2 = 0; q2 < 4; q2++) { dH[c][q2] = 0.f; dL[c][q2] = 0.f; }

#pragma unroll 4
        for (int j = 0; j < 16; j++) {
#pragma unroll
            for (int ch = 0; ch < 4; ch++) {
                int ks = ch * 16 + j;
                uint4 aH = __ldg(WA + (ks * 2 + 0) * 32 + lane);
                uint4 aL = __ldg(WA + (ks * 2 + 1) * 32 + lane);
                uint4 bF = ldg128cg(SB + (ks * 4 + gphalf) * 32 + lane);
                uint32_t r0 = sel ? bF.z : bF.x;
                uint32_t r1 = sel ? bF.w : bF.y;
                mma_acc(dH[ch], aH, r0, r1);
                mma_acc(dL[ch], aL, r0, r1);
            }
        }

        // combine chains: z[0]=zh(b0), z[1]=zh(b1), z[2]=zt(b0), z[3]=zt(b1)
        float z[4];
#pragma unroll
        for (int q2 = 0; q2 < 4; q2++)
            z[q2] = (dH[0][q2] + dH[1][q2]) + (dH[2][q2] + dH[3][q2])
                  + (dL[0][q2] + dL[1][q2]) + (dL[2][q2] + dL[3][q2]);

        if (l == 0) {
            z[0] += peh0; z[1] += peh1; z[2] += pet0; z[3] += pet1;
        } else if (l == 1) {
            z[0] += bh1v; z[1] += bh1v; z[2] += bt1v; z[3] += bt1v;
        } else {
            z[0] += bh2v; z[1] += bh2v; z[2] += bt2v; z[3] += bt2v;
        }

        float sn0, sn1;
        {
            float tg0 = sigm_ap(z[2]);
            float tg1 = sigm_ap(z[3]);
            sn0 = (tanh_ap(z[0]) - sold0) * tg0 + sold0;
            sn1 = (tanh_ap(z[1]) - sold1) * tg1 + sold1;
            sold0 = sn0; sold1 = sn1;
        }
        if (l == 2) { stage_st[b0][g] = sn0; stage_st[b1][g] = sn1; }

        // pack + neighbor exchange (c-even, c-odd pairs)
        {
            uint32_t h0 = (uint32_t)__bfloat16_as_ushort(__float2bfloat16(sn0));
            uint32_t h1 = (uint32_t)__bfloat16_as_ushort(__float2bfloat16(sn1));
            uint32_t oth0 = __shfl_xor_sync(0xffffffffu, h0, 4);
            uint32_t oth1 = __shfl_xor_sync(0xffffffffu, h1, 4);
            uint32_t word = (g & 1) ? ((h1 << 16) | oth1)
                                    : ((oth0 << 16) | h0);
            sOut[sidx] = word;
        }

        // prefetch next timestep's Eh/Et during l==1
        if (l == 1) {
            int tq = (t < T_ - 1) ? t + 1 : t;
            int v0 = __ldg(&input_data[b0 * T_ + tq]);
            int v1 = __ldg(&input_data[b1 * T_ + tq]);
            peh0 = __ldg(&Eh[(size_t)v0 * R_ + col]);
            pet0 = __ldg(&Et[(size_t)v0 * R_ + col]);
            peh1 = __ldg(&Eh[(size_t)v1 * R_ + col]);
            pet1 = __ldg(&Et[(size_t)v1 * R_ + col]);
        }

        pc++;
        grid_sync(RCTA * pc, &g_bar);
        if (++l == 3) { l = 0; t++; }
    }

    // final timestep's states write
    if (tid < 128) {
        int rb = tid >> 1, half = tid & 1;
        *(float4*)&states[((size_t)(T_ - 1) * B_ + rb) * R_ + cbase + half * 4] =
            *(float4*)&stage_st[rb][half * 4];
    }
}

// ---------------------------------------------------------------------------
// Loss (single-pass online softmax) + mean
// ---------------------------------------------------------------------------
__global__ __launch_bounds__(256)
void loss_kernel(const float* __restrict__ outb,
                 const float* __restrict__ logits,
                 const int* __restrict__ targets,
                 const int* __restrict__ sampled,
                 const float* __restrict__ true_counts,
                 const float* __restrict__ sw,
                 const float* __restrict__ softmax_b,
                 float* __restrict__ loss) {
    __shared__ float rm[256], rs[256];
    __shared__ float sh_true;
    const int i = blockIdx.x;
    const int tid = threadIdx.x;
    const int label = targets[i];

    float pdot = 0.f;
    for (int u = tid; u < U_; u += 256)
        pdot += outb[(size_t)i * U_ + u] * sw[(size_t)label * U_ + u];
    rm[tid] = pdot; __syncthreads();
    for (int s = 128; s > 0; s >>= 1) {
        if (tid < s) rm[tid] += rm[tid + s];
        __syncthreads();
    }
    if (tid == 0) sh_true = rm[0] + softmax_b[label] - logf(true_counts[i]);
    __syncthreads();
    const float tl = sh_true;

    float m = -1e30f, ssum = 0.f;
    for (int j = tid; j < S_; j += 256) {
        float v = logits[(size_t)i * S_ + j];
        if (sampled[j] == label) v -= 1e9f;
        if (v <= m) {
            ssum += __expf(v - m);
        } else {
            ssum = ssum * __expf(m - v) + 1.f;
            m = v;
        }
    }
    rm[tid] = m; rs[tid] = ssum;
    __syncthreads();
    for (int s = 128; s > 0; s >>= 1) {
        if (tid < s) {
            float m2 = rm[tid + s], s2 = rs[tid + s];
            float m1 = rm[tid], s1 = rs[tid];
            float nm = fmaxf(m1, m2);
            rs[tid] = s1 * __expf(m1 - nm) + s2 * __expf(m2 - nm);
            rm[tid] = nm;
        }
        __syncthreads();
    }
    if (tid == 0) {
        float m0 = rm[0], s0 = rs[0];
        float nm = fmaxf(m0, tl);
        float total = s0 * __expf(m0 - nm) + __expf(tl - nm);
        loss[i] = nm + logf(total) - tl;
    }
}

__global__ void reduce_mean_kernel(const float* __restrict__ loss, float* __restrict__ out) {
    __shared__ float red[256];
    const int tid = threadIdx.x;
    float s = 0.f;
    for (int i = tid; i < N_; i += 256) s += loss[i];
    red[tid] = s; __syncthreads();
    for (int st = 128; st > 0; st >>= 1) {
        if (tid < st) red[tid] += red[tid + st];
        __syncthreads();
    }
    if (tid == 0) out[0] = red[0] / (float)N_;
}

// ---------------------------------------------------------------------------
// Launch
// ---------------------------------------------------------------------------
extern "C" void kernel_launch(void* const* d_in, const int* in_sizes, int n_in,
                              void* d_out, int out_size) {
    const int*   input_data = (const int*)d_in[0];
    const int*   targets    = (const int*)d_in[1];
    const int*   sampled    = (const int*)d_in[2];
    const float* true_cnt   = (const float*)d_in[3];
    const float* samp_cnt   = (const float*)d_in[4];
    const float* embedding  = (const float*)d_in[5];
    const float* Wh0        = (const float*)d_in[6];
    const float* bh0        = (const float*)d_in[7];
    const float* Wt0        = (const float*)d_in[8];
    const float* bt0        = (const float*)d_in[9];
    const float* Wh         = (const float*)d_in[10];
    const float* bh         = (const float*)d_in[11];
    const float* Wt         = (const float*)d_in[12];
    const float* bt         = (const float*)d_in[13];
    const float* Wp         = (const float*)d_in[14];
    const float* bp         = (const float*)d_in[15];
    const float* sw         = (const float*)d_in[16];
    const float* smb        = (const float*)d_in[17];
    float* out = (float*)d_out;

    float *Eh, *Et, *states, *outb, *logits, *sbv, *lossv;
    uint32_t *Wf, *Sf;
    uint4 *BfEh, *BfEt, *BfOp, *BfLg;
    uint4 *AembH, *AstH, *AobH;
    cudaGetSymbolAddress((void**)&Eh, g_Eh);
    cudaGetSymbolAddress((void**)&Et, g_Et);
    cudaGetSymbolAddress((void**)&states, g_states);
    cudaGetSymbolAddress((void**)&outb, g_outb);
    cudaGetSymbolAddress((void**)&logits, g_logits);
    cudaGetSymbolAddress((void**)&sbv, g_sbv);
    cudaGetSymbolAddress((void**)&lossv, g_loss);
    cudaGetSymbolAddress((void**)&Wf, g_Wf);
    cudaGetSymbolAddress((void**)&Sf, g_Sf);
    cudaGetSymbolAddress((void**)&BfEh, g_Bf_eh);
    cudaGetSymbolAddress((void**)&BfEt, g_Bf_et);
    cudaGetSymbolAddress((void**)&BfOp, g_Bf_op);
    cudaGetSymbolAddress((void**)&BfLg, g_Bf_lg);
    cudaGetSymbolAddress((void**)&AembH, g_Aemb_h);
    cudaGetSymbolAddress((void**)&AstH, g_Ast_h);
    cudaGetSymbolAddress((void**)&AobH, g_Aob_h);

    init_kernel<<<(2 * 32768 + 255) / 256, 256>>>(Sf);
    sb_kernel<<<(S_ + 255) / 256, 256>>>(sampled, smb, samp_cnt, sbv);
    wcvt_kernel<<<384, 256>>>(Wh0, Wt0, Wh, Wt, Wf);

    // B fragment preps
    prep_b_kn<<<512, 256>>>(Wh0, BfEh, U_, R_, R_);
    prep_b_kn<<<512, 256>>>(Wt0, BfEt, U_, R_, R_);
    prep_b_kn<<<512, 256>>>(Wp, BfOp, R_, U_, U_);
    prep_b_gather<<<512, 256>>>(sw, sampled, BfLg);

    // A fragment prep: embedding
    prep_a<0><<<2000, 256>>>(embedding, AembH, V_, U_, U_);

    // Vocab-space x-part precompute
    {
        dim3 grid(R_ / 64, V_ / 64);
        tgemm_f<0><<<grid, 256>>>(AembH, BfEh, bh0, Eh, nullptr, V_, R_, U_, R_);
        tgemm_f<0><<<grid, 256>>>(AembH, BfEt, bt0, Et, nullptr, V_, R_, U_, R_);
    }

    // Persistent recurrence (batch-split warps, register epilogue)
    rec_mma_kernel<<<RCTA, RTHR>>>(Wf, Sf, input_data, Eh, Et, bh, bt, states);

    // states -> A fragments (remap)
    prep_a<1><<<8192, 256>>>(states, AstH, N_, R_, R_);

    // outputs = states @ Wp + bp ; emits outb A-fragments
    {
        dim3 grid(U_ / 64, N_ / 64);
        tgemm_f<1><<<grid, 256>>>(AstH, BfOp, bp, outb, AobH, N_, U_, R_, U_);
    }
    // sampled logits = outb @ sw[sampled].T + sbv
    {
        dim3 grid(S_ / 64, N_ / 64);
        tgemm_f<0><<<grid, 256>>>(AobH, BfLg, sbv, logits, nullptr, N_, S_, U_, S_);
    }

    loss_kernel<<<N_, 256>>>(outb, logits, targets, sampled, true_cnt, sw, smb, lossv);
    reduce_mean_kernel<<<1, 256>>>(lossv, out);
}

// round 16
// speedup vs baseline: 1.4468x; 1.4468x over previous
#include <cuda_runtime.h>
#include <cuda_bf16.h>
#include <math.h>
#include <stdint.h>

#define V_ 8000
#define B_ 64
#define T_ 256
#define R_ 1024
#define U_ 512
#define S_ 1024
#define N_ (B_ * T_)

#define RCTA 128
#define RTHR 256

// ---------------------------------------------------------------------------
// Device global scratch
// ---------------------------------------------------------------------------
__device__ float g_Eh[(size_t)V_ * R_];
__device__ float g_Et[(size_t)V_ * R_];
__device__ uint32_t g_Wf[(size_t)3 * 128 * 16384];
__device__ uint32_t g_Sf[2 * 32768];
__device__ float g_outb[(size_t)N_ * U_];
__device__ float g_logits[(size_t)N_ * S_];
__device__ float g_sbv[S_];
__device__ float g_loss[N_];
__device__ unsigned int g_bar;
// B fragment buffers: [K/16][N/8][lane32] uint4{hi0,hi1,lo0,lo1}
__device__ uint4 g_Bf_eh[131072];
__device__ uint4 g_Bf_et[131072];
__device__ uint4 g_Bf_op[131072];
__device__ uint4 g_Bf_lg[131072];
// A fragment planes (bf16 hi only): [M/16][K/16][lane32] uint4
__device__ uint4 g_Aemb_h[512000];
__device__ uint4 g_Ast_h[2097152];   // states fragments, emitted by recurrence
__device__ uint4 g_Aob_h[1048576];

// ---------------------------------------------------------------------------
// PTX helpers
// ---------------------------------------------------------------------------
__device__ __forceinline__ void mma_acc(float* d, const uint4& a, uint32_t b0, uint32_t b1) {
    asm volatile(
        "mma.sync.aligned.m16n8k16.row.col.f32.bf16.bf16.f32 "
        "{%0,%1,%2,%3},{%4,%5,%6,%7},{%8,%9},{%0,%1,%2,%3};"
        : "+f"(d[0]), "+f"(d[1]), "+f"(d[2]), "+f"(d[3])
        : "r"(a.x), "r"(a.y), "r"(a.z), "r"(a.w), "r"(b0), "r"(b1));
}
__device__ __forceinline__ uint4 ldg128cg(const uint4* p) {
    uint4 v;
    asm volatile("ld.global.cg.v4.u32 {%0,%1,%2,%3}, [%4];"
                 : "=r"(v.x), "=r"(v.y), "=r"(v.z), "=r"(v.w) : "l"(p));
    return v;
}
__device__ __forceinline__ float2 ldcg64f(const float* p) {
    float2 v;
    asm volatile("ld.global.cg.v2.f32 {%0,%1}, [%2];" : "=f"(v.x), "=f"(v.y) : "l"(p));
    return v;
}
__device__ __forceinline__ void grid_sync(unsigned int target, unsigned int* bar) {
    __syncthreads();
    if (threadIdx.x == 0) {
        asm volatile("red.release.gpu.global.add.u32 [%0], 1;" :: "l"(bar) : "memory");
        unsigned int v;
        do {
            asm volatile("ld.acquire.gpu.global.u32 %0, [%1];" : "=r"(v) : "l"(bar) : "memory");
        } while (v < target);
    }
    __syncthreads();
}
__device__ __forceinline__ uint32_t pack_hi(float x0, float x1) {
    uint16_t h0 = __bfloat16_as_ushort(__float2bfloat16(x0));
    uint16_t h1 = __bfloat16_as_ushort(__float2bfloat16(x1));
    return ((uint32_t)h1 << 16) | h0;
}
__device__ __forceinline__ uint32_t pack_lo(float x0, float x1) {
    float r0 = x0 - __bfloat162float(__float2bfloat16(x0));
    float r1 = x1 - __bfloat162float(__float2bfloat16(x1));
    return pack_hi(r0, r1);
}
__device__ __forceinline__ float tanh_ap(float x) {
    float y;
    asm("tanh.approx.f32 %0, %1;" : "=f"(y) : "f"(x));
    return y;
}
__device__ __forceinline__ float sigm_ap(float x) {
    float e;
    asm("ex2.approx.f32 %0, %1;" : "=f"(e) : "f"(-x * 1.4426950408889634f));
    float r;
    asm("rcp.approx.f32 %0, %1;" : "=f"(r) : "f"(1.f + e));
    return r;
}

// ---------------------------------------------------------------------------
// Setup kernels
// ---------------------------------------------------------------------------
__global__ void init_kernel(uint32_t* sf) {
    int i = blockIdx.x * 256 + threadIdx.x;
    if (i == 0) g_bar = 0u;
    if (i < 2 * 32768) sf[i] = 0u;
}

__global__ void sb_kernel(const int* __restrict__ sampled,
                          const float* __restrict__ softmax_b,
                          const float* __restrict__ scounts,
                          float* __restrict__ sbv) {
    int j = blockIdx.x * 256 + threadIdx.x;
    if (j < S_) sbv[j] = softmax_b[sampled[j]] - logf(scounts[j]);
}

// B-fragment prep from row-major src[k][n]
__global__ __launch_bounds__(256)
void prep_b_kn(const float* __restrict__ src, uint4* __restrict__ out,
               int K, int N, int ldb) {
    int idx = blockIdx.x * 256 + threadIdx.x;
    int total = (K >> 4) * (N >> 3) * 32;
    if (idx >= total) return;
    int lane = idx & 31;
    int nt = (idx >> 5) % (N >> 3);
    int gks = (idx >> 5) / (N >> 3);
    int g = lane >> 2, tg = lane & 3;
    int n = nt * 8 + g;
    int k0 = gks * 16 + tg * 2;
    float a0 = src[(size_t)k0 * ldb + n];
    float a1 = src[(size_t)(k0 + 1) * ldb + n];
    float a2 = src[(size_t)(k0 + 8) * ldb + n];
    float a3 = src[(size_t)(k0 + 9) * ldb + n];
    out[idx] = make_uint4(pack_hi(a0, a1), pack_hi(a2, a3),
                          pack_lo(a0, a1), pack_lo(a2, a3));
}

__global__ __launch_bounds__(256)
void prep_b_gather(const float* __restrict__ sw, const int* __restrict__ sampled,
                   uint4* __restrict__ out) {
    int idx = blockIdx.x * 256 + threadIdx.x;
    const int K = U_, N = S_;
    int total = (K >> 4) * (N >> 3) * 32;
    if (idx >= total) return;
    int lane = idx & 31;
    int nt = (idx >> 5) % (N >> 3);
    int gks = (idx >> 5) / (N >> 3);
    int g = lane >> 2, tg = lane & 3;
    int n = nt * 8 + g;
    int k0 = gks * 16 + tg * 2;
    const float* row = sw + (size_t)sampled[n] * U_;
    float a0 = row[k0], a1 = row[k0 + 1], a2 = row[k0 + 8], a3 = row[k0 + 9];
    out[idx] = make_uint4(pack_hi(a0, a1), pack_hi(a2, a3),
                          pack_lo(a0, a1), pack_lo(a2, a3));
}

// A-fragment prep (hi plane only), plain row-major source.
__global__ __launch_bounds__(256)
void prep_a0(const float* __restrict__ src, uint4* __restrict__ hi,
             int M, int K, int lda) {
    int idx = blockIdx.x * 256 + threadIdx.x;
    int total = (M >> 4) * (K >> 4) * 32;
    if (idx >= total) return;
    int lane = idx & 31;
    int kt = (idx >> 5) % (K >> 4);
    int mt = (idx >> 5) / (K >> 4);
    int r = lane >> 2;
    int k0 = kt * 16 + (lane & 3) * 2;
    int row0 = mt * 16 + r, row1 = row0 + 8;
    const float* p0 = src + (size_t)row0 * lda;
    const float* p1 = src + (size_t)row1 * lda;
    float2 v0 = *(const float2*)(p0 + k0);
    float2 v1 = *(const float2*)(p1 + k0);
    float2 v2 = *(const float2*)(p0 + k0 + 8);
    float2 v3 = *(const float2*)(p1 + k0 + 8);
    hi[idx] = make_uint4(pack_hi(v0.x, v0.y), pack_hi(v1.x, v1.y),
                         pack_hi(v2.x, v2.y), pack_hi(v3.x, v3.y));
}

// Weight -> fragment-linear bf16 hi/lo for recurrence.
__global__ __launch_bounds__(256)
void wcvt_kernel(const float* __restrict__ Wh0, const float* __restrict__ Wt0,
                 const float* __restrict__ Wh,  const float* __restrict__ Wt,
                 uint32_t* __restrict__ Wf) {
    __shared__ float ws[256][17];
    int b = blockIdx.x;
    int cta = b & 127;
    int l = b >> 7;
    int cbase = cta * 8;
    int tid = threadIdx.x;
    uint32_t* outp = Wf + (size_t)(l * 128 + cta) * 16384;

    for (int kb = 0; kb < 4; kb++) {
#pragma unroll
        for (int e = 0; e < 16; e++) {
            int idx = tid + e * 256;
            int k = idx >> 4, cg = idx & 15;
            int g = cg >> 3, c = cg & 7;
            int kg = kb * 256 + k;
            float v;
            if (l == 0) v = (g ? Wt0 : Wh0)[(size_t)(U_ + kg) * R_ + cbase + c];
            else        v = (g ? Wt : Wh)[((size_t)(l - 1) * R_ + kg) * R_ + cbase + c];
            ws[k][g * 8 + c] = v;
        }
        __syncthreads();
#pragma unroll
        for (int e = 0; e < 16; e++) {
            int o = tid + e * 256;
            int ksl = o >> 8;
            int rem = o & 255;
            int term = rem >> 7;
            int rem2 = rem & 127;
            int lane = rem2 >> 2;
            int r = rem2 & 3;
            int gate = r & 1;
            int c = lane >> 2;
            int kk = (lane & 3) * 2 + (r >> 1) * 8;
            int kl = ksl * 16 + kk;
            float w0 = ws[kl][gate * 8 + c];
            float w1 = ws[kl + 1][gate * 8 + c];
            uint32_t val = term ? pack_lo(w0, w1) : pack_hi(w0, w1);
            int ks = kb * 16 + ksl;
            outp[((ks * 2 + term) * 32 + lane) * 4 + r] = val;
        }
        __syncthreads();
    }
}

// ---------------------------------------------------------------------------
// Fragment tensor GEMM (2-term: Ahi*(Bhi+Blo)). No smem, no syncs.
// ---------------------------------------------------------------------------
template <int EMITC>
__global__ __launch_bounds__(256)
void tgemm_f(const uint4* __restrict__ Ah, const uint4* __restrict__ Bf,
             const float* __restrict__ bias, float* __restrict__ C,
             uint4* __restrict__ Ch, int M, int N, int K, int ldc) {
    const int tid = threadIdx.x;
    const int lane = tid & 31;
    const int w = tid >> 5;
    const int mh = w >> 2;
    const int nq = w & 3;
    const int bm = blockIdx.y * 64;
    const int bn = blockIdx.x * 64;
    const int KT = K >> 4, NT = N >> 3;

    const int mt0 = (bm >> 4) + mh * 2;
    const uint4* A0h = Ah + ((size_t)mt0 * KT) * 32 + lane;
    const uint4* A1h = A0h + (size_t)KT * 32;
    const uint4* Bp0 = Bf + ((size_t)(bn >> 3) + nq * 2) * 32 + lane;

    float d[2][2][4];
#pragma unroll
    for (int i = 0; i < 2; i++)
#pragma unroll
        for (int j = 0; j < 2; j++)
#pragma unroll
            for (int q = 0; q < 4; q++) d[i][j][q] = 0.f;

#pragma unroll 4
    for (int kt = 0; kt < KT; kt++) {
        uint4 aH0 = __ldg(A0h + kt * 32);
        uint4 aH1 = __ldg(A1h + kt * 32);
        uint4 b0 = ldg128cg(Bp0 + (size_t)kt * NT * 32);
        uint4 b1 = ldg128cg(Bp0 + (size_t)kt * NT * 32 + 32);
        mma_acc(d[0][0], aH0, b0.x, b0.y);
        mma_acc(d[0][0], aH0, b0.z, b0.w);
        mma_acc(d[0][1], aH0, b1.x, b1.y);
        mma_acc(d[0][1], aH0, b1.z, b1.w);
        mma_acc(d[1][0], aH1, b0.x, b0.y);
        mma_acc(d[1][0], aH1, b0.z, b0.w);
        mma_acc(d[1][1], aH1, b1.x, b1.y);
        mma_acc(d[1][1], aH1, b1.z, b1.w);
    }

    const int g = lane >> 2, tg = lane & 3;
#pragma unroll
    for (int mti = 0; mti < 2; mti++) {
        int row0 = bm + (mh * 2 + mti) * 16 + g;
        float v[2][4];
#pragma unroll
        for (int nti = 0; nti < 2; nti++) {
            int col = bn + nq * 16 + nti * 8 + tg * 2;
            float b0v = bias ? bias[col] : 0.f;
            float b1v = bias ? bias[col + 1] : 0.f;
            v[nti][0] = d[mti][nti][0] + b0v;
            v[nti][1] = d[mti][nti][1] + b1v;
            v[nti][2] = d[mti][nti][2] + b0v;
            v[nti][3] = d[mti][nti][3] + b1v;
            C[(size_t)row0 * ldc + col]           = v[nti][0];
            C[(size_t)row0 * ldc + col + 1]       = v[nti][1];
            C[(size_t)(row0 + 8) * ldc + col]     = v[nti][2];
            C[(size_t)(row0 + 8) * ldc + col + 1] = v[nti][3];
        }
        if (EMITC) {
            int KT2 = N >> 4;
            int mtile = (bm >> 4) + mh * 2 + mti;
            int ktile = (bn >> 4) + nq;
            size_t fi = ((size_t)mtile * KT2 + ktile) * 32 + lane;
            Ch[fi] = make_uint4(pack_hi(v[0][0], v[0][1]), pack_hi(v[0][2], v[0][3]),
                                pack_hi(v[1][0], v[1][1]), pack_hi(v[1][2], v[1][3]));
        }
    }
}

// ---------------------------------------------------------------------------
// Persistent recurrence (R11 structure: 8-warp K-split, smem partials).
// NEW: at l==2 the epilogue emits the states A-fragment u32 directly
// (replaces the fp32 states array + prep_a remap kernel entirely).
// ---------------------------------------------------------------------------
__global__ __launch_bounds__(RTHR, 1)
void rec_mma_kernel(const uint32_t* __restrict__ Wf,
                    uint32_t* __restrict__ Sf,
                    const int* __restrict__ input_data,
                    const float* __restrict__ Eh, const float* __restrict__ Et,
                    const float* __restrict__ bh, const float* __restrict__ bt,
                    uint32_t* __restrict__ AstF) {
    __shared__ float part[8][16][68];
    __shared__ float sold[64][9];
    __shared__ float bias_s[32];

    const int tid = threadIdx.x;
    const int lane = tid & 31;
    const int w = tid >> 5;
    const int cta = blockIdx.x;
    const int cbase = cta * 8;
    const int eb = tid & 63;
    const int ec0 = (tid >> 6) * 2;

    for (int i = tid; i < 64 * 9; i += RTHR) ((float*)sold)[i] = 0.f;
    if (tid < 32) {
        int l2 = tid >> 4, g = (tid >> 3) & 1, c = tid & 7;
        bias_s[tid] = (g ? bt : bh)[l2 * R_ + cbase + c];
    }
    __syncthreads();

    float2 pe_h, pe_t;
    {
        int vid = __ldg(&input_data[eb * T_ + 0]);
        pe_h = ldcg64f(&Eh[(size_t)vid * R_ + cbase + ec0]);
        pe_t = ldcg64f(&Et[(size_t)vid * R_ + cbase + ec0]);
    }

    // constant part of the Ast-fragment index for this thread:
    // row = eb*T + t ; k = cbase + ec0
    const int kglob = cbase + ec0;
    const int ktile = kglob >> 4;
    const int kk = kglob & 15;
    const int lane_k = (kk >> 1) & 3;         // lane low bits from k
    const int comp_k = (kk & 8) ? 2 : 0;      // x/y vs z/w
    const int mt_base = eb * 16;              // (eb*T)>>4

    unsigned int pc = 0;
    int t = 0, l = 0;

    for (int p = 0; p < 3 * T_; p++) {
        const int rbuf = p & 1;
        const uint4* SB = (const uint4*)(Sf + rbuf * 32768);
        uint32_t* sOut = Sf + (rbuf ^ 1) * 32768;
        const uint4* WA = (const uint4*)Wf + (size_t)(l * 128 + cta) * 4096;

        float dH[8][4], dL[8][4];
#pragma unroll
        for (int g = 0; g < 8; g++)
#pragma unroll
            for (int q = 0; q < 4; q++) { dH[g][q] = 0.f; dL[g][q] = 0.f; }

        const int ks0 = w * 8;
#pragma unroll 4
        for (int j = 0; j < 8; j++) {
            int ks = ks0 + j;
            uint4 aH = __ldg(WA + (ks * 2 + 0) * 32 + lane);
            uint4 aL = __ldg(WA + (ks * 2 + 1) * 32 + lane);
            uint4 bF[4];
#pragma unroll
            for (int gp = 0; gp < 4; gp++)
                bF[gp] = ldg128cg(SB + (ks * 4 + gp) * 32 + lane);
#pragma unroll
            for (int gp = 0; gp < 4; gp++) {
                mma_acc(dH[2 * gp],     aH, bF[gp].x, bF[gp].y);
                mma_acc(dH[2 * gp + 1], aH, bF[gp].z, bF[gp].w);
                mma_acc(dL[2 * gp],     aL, bF[gp].x, bF[gp].y);
                mma_acc(dL[2 * gp + 1], aL, bF[gp].z, bF[gp].w);
            }
        }

        {
            int row = lane >> 2;
            int nb = (lane & 3) * 2;
#pragma unroll
            for (int g = 0; g < 8; g++) {
                *(float2*)&part[w][row][nb + g * 8] =
                    make_float2(dH[g][0] + dL[g][0], dH[g][1] + dL[g][1]);
                *(float2*)&part[w][row + 8][nb + g * 8] =
                    make_float2(dH[g][2] + dL[g][2], dH[g][3] + dL[g][3]);
            }
        }
        __syncthreads();

        {
            float snv[2];
            uint16_t sh[2];
#pragma unroll
            for (int s = 0; s < 2; s++) {
                int c = ec0 + s;
                float zh = 0.f, zt = 0.f;
#pragma unroll
                for (int q = 0; q < 8; q++) {
                    zh += part[q][c][eb];
                    zt += part[q][8 + c][eb];
                }
                if (l == 0) {
                    zh += (s == 0) ? pe_h.x : pe_h.y;
                    zt += (s == 0) ? pe_t.x : pe_t.y;
                } else {
                    zh += bias_s[(l - 1) * 16 + c];
                    zt += bias_s[(l - 1) * 16 + 8 + c];
                }
                float so = sold[eb][c];
                float hh = tanh_ap(zh);
                float tg = sigm_ap(zt);
                float sn = (hh - so) * tg + so;
                sold[eb][c] = sn;
                snv[s] = sn;
                sh[s] = __bfloat16_as_ushort(__float2bfloat16(sn));
            }
            uint32_t word = ((uint32_t)sh[1] << 16) | sh[0];

            // state fragment for next phase's MMA
            {
                int kk0 = (cta & 1) * 8 + ec0;
                int q = (kk0 >> 1) & 3;
                int reg = cta & 1;
                int g = eb >> 3;
                int lt = (eb & 7) * 4 + q;
                int ks = cta >> 1;
                int slot = (g & 1) * 2 + reg;
                int gp = g >> 1;
                sOut[(uint32_t)(((ks * 4 + gp) * 32 + lt) * 4 + slot)] = word;
            }

            // outproj A-fragment emission at l==2 (row = eb*T + t)
            if (l == 2) {
                int rin = t & 15;
                int mt = mt_base + (t >> 4);
                int lane2 = ((rin & 7) << 2) | lane_k;
                int comp = comp_k + ((rin & 8) ? 1 : 0);
                size_t fi = (((size_t)mt * 64 + ktile) * 32 + lane2) * 4 + comp;
                AstF[fi] = word;
            }
        }

        if (l == 1) {
            int tq = (t < T_ - 1) ? t + 1 : t;
            int vid = __ldg(&input_data[eb * T_ + tq]);
            pe_h = ldcg64f(&Eh[(size_t)vid * R_ + cbase + ec0]);
            pe_t = ldcg64f(&Et[(size_t)vid * R_ + cbase + ec0]);
        }

        pc++;
        grid_sync(RCTA * pc, &g_bar);
        if (++l == 3) { l = 0; t++; }
    }
}

// ---------------------------------------------------------------------------
// Loss (single-pass online softmax) + mean
// ---------------------------------------------------------------------------
__global__ __launch_bounds__(256)
void loss_kernel(const float* __restrict__ outb,
                 const float* __restrict__ logits,
                 const int* __restrict__ targets,
                 const int* __restrict__ sampled,
                 const float* __restrict__ true_counts,
                 const float* __restrict__ sw,
                 const float* __restrict__ softmax_b,
                 float* __restrict__ loss) {
    __shared__ float rm[256], rs[256];
    __shared__ float sh_true;
    const int i = blockIdx.x;
    const int tid = threadIdx.x;
    const int label = targets[i];

    float pdot = 0.f;
    for (int u = tid; u < U_; u += 256)
        pdot += outb[(size_t)i * U_ + u] * sw[(size_t)label * U_ + u];
    rm[tid] = pdot; __syncthreads();
    for (int s = 128; s > 0; s >>= 1) {
        if (tid < s) rm[tid] += rm[tid + s];
        __syncthreads();
    }
    if (tid == 0) sh_true = rm[0] + softmax_b[label] - logf(true_counts[i]);
    __syncthreads();
    const float tl = sh_true;

    float m = -1e30f, ssum = 0.f;
    for (int j = tid; j < S_; j += 256) {
        float v = logits[(size_t)i * S_ + j];
        if (sampled[j] == label) v -= 1e9f;
        if (v <= m) {
            ssum += __expf(v - m);
        } else {
            ssum = ssum * __expf(m - v) + 1.f;
            m = v;
        }
    }
    rm[tid] = m; rs[tid] = ssum;
    __syncthreads();
    for (int s = 128; s > 0; s >>= 1) {
        if (tid < s) {
            float m2 = rm[tid + s], s2 = rs[tid + s];
            float m1 = rm[tid], s1 = rs[tid];
            float nm = fmaxf(m1, m2);
            rs[tid] = s1 * __expf(m1 - nm) + s2 * __expf(m2 - nm);
            rm[tid] = nm;
        }
        __syncthreads();
    }
    if (tid == 0) {
        float m0 = rm[0], s0 = rs[0];
        float nm = fmaxf(m0, tl);
        float total = s0 * __expf(m0 - nm) + __expf(tl - nm);
        loss[i] = nm + logf(total) - tl;
    }
}

__global__ void reduce_mean_kernel(const float* __restrict__ loss, float* __restrict__ out) {
    __shared__ float red[256];
    const int tid = threadIdx.x;
    float s = 0.f;
    for (int i = tid; i < N_; i += 256) s += loss[i];
    red[tid] = s; __syncthreads();
    for (int st = 128; st > 0; st >>= 1) {
        if (tid < st) red[tid] += red[tid + st];
        __syncthreads();
    }
    if (tid == 0) out[0] = red[0] / (float)N_;
}

// ---------------------------------------------------------------------------
// Launch
// ---------------------------------------------------------------------------
extern "C" void kernel_launch(void* const* d_in, const int* in_sizes, int n_in,
                              void* d_out, int out_size) {
    const int*   input_data = (const int*)d_in[0];
    const int*   targets    = (const int*)d_in[1];
    const int*   sampled    = (const int*)d_in[2];
    const float* true_cnt   = (const float*)d_in[3];
    const float* samp_cnt   = (const float*)d_in[4];
    const float* embedding  = (const float*)d_in[5];
    const float* Wh0        = (const float*)d_in[6];
    const float* bh0        = (const float*)d_in[7];
    const float* Wt0        = (const float*)d_in[8];
    const float* bt0        = (const float*)d_in[9];
    const float* Wh         = (const float*)d_in[10];
    const float* bh         = (const float*)d_in[11];
    const float* Wt         = (const float*)d_in[12];
    const float* bt         = (const float*)d_in[13];
    const float* Wp         = (const float*)d_in[14];
    const float* bp         = (const float*)d_in[15];
    const float* sw         = (const float*)d_in[16];
    const float* smb        = (const float*)d_in[17];
    float* out = (float*)d_out;

    float *Eh, *Et, *outb, *logits, *sbv, *lossv;
    uint32_t *Wf, *Sf;
    uint4 *BfEh, *BfEt, *BfOp, *BfLg;
    uint4 *AembH, *AstH, *AobH;
    cudaGetSymbolAddress((void**)&Eh, g_Eh);
    cudaGetSymbolAddress((void**)&Et, g_Et);
    cudaGetSymbolAddress((void**)&outb, g_outb);
    cudaGetSymbolAddress((void**)&logits, g_logits);
    cudaGetSymbolAddress((void**)&sbv, g_sbv);
    cudaGetSymbolAddress((void**)&lossv, g_loss);
    cudaGetSymbolAddress((void**)&Wf, g_Wf);
    cudaGetSymbolAddress((void**)&Sf, g_Sf);
    cudaGetSymbolAddress((void**)&BfEh, g_Bf_eh);
    cudaGetSymbolAddress((void**)&BfEt, g_Bf_et);
    cudaGetSymbolAddress((void**)&BfOp, g_Bf_op);
    cudaGetSymbolAddress((void**)&BfLg, g_Bf_lg);
    cudaGetSymbolAddress((void**)&AembH, g_Aemb_h);
    cudaGetSymbolAddress((void**)&AstH, g_Ast_h);
    cudaGetSymbolAddress((void**)&AobH, g_Aob_h);

    init_kernel<<<(2 * 32768 + 255) / 256, 256>>>(Sf);
    sb_kernel<<<(S_ + 255) / 256, 256>>>(sampled, smb, samp_cnt, sbv);
    wcvt_kernel<<<384, 256>>>(Wh0, Wt0, Wh, Wt, Wf);

    // B fragment preps
    prep_b_kn<<<512, 256>>>(Wh0, BfEh, U_, R_, R_);
    prep_b_kn<<<512, 256>>>(Wt0, BfEt, U_, R_, R_);
    prep_b_kn<<<512, 256>>>(Wp, BfOp, R_, U_, U_);
    prep_b_gather<<<512, 256>>>(sw, sampled, BfLg);

    // A fragment prep: embedding
    prep_a0<<<2000, 256>>>(embedding, AembH, V_, U_, U_);

    // Vocab-space x-part precompute
    {
        dim3 grid(R_ / 64, V_ / 64);
        tgemm_f<0><<<grid, 256>>>(AembH, BfEh, bh0, Eh, nullptr, V_, R_, U_, R_);
        tgemm_f<0><<<grid, 256>>>(AembH, BfEt, bt0, Et, nullptr, V_, R_, U_, R_);
    }

    // Persistent recurrence — emits states A-fragments directly
    rec_mma_kernel<<<RCTA, RTHR>>>(Wf, Sf, input_data, Eh, Et, bh, bt,
                                   (uint32_t*)AstH);

    // outputs = states @ Wp + bp ; emits outb A-fragments
    {
        dim3 grid(U_ / 64, N_ / 64);
        tgemm_f<1><<<grid, 256>>>(AstH, BfOp, bp, outb, AobH, N_, U_, R_, U_);
    }
    // sampled logits = outb @ sw[sampled].T + sbv
    {
        dim3 grid(S_ / 64, N_ / 64);
        tgemm_f<0><<<grid, 256>>>(AobH, BfLg, sbv, logits, nullptr, N_, S_, U_, S_);
    }

    loss_kernel<<<N_, 256>>>(outb, logits, targets, sampled, true_cnt, sw, smb, lossv);
    reduce_mean_kernel<<<1, 256>>>(lossv, out);
}

// round 17
// speedup vs baseline: 1.6068x; 1.1106x over previous
#include <cuda_runtime.h>
#include <cuda_bf16.h>
#include <math.h>
#include <stdint.h>

#define V_ 8000
#define B_ 64
#define T_ 256
#define R_ 1024
#define U_ 512
#define S_ 1024
#define N_ (B_ * T_)

#define RCTA 128
#define RTHR 256

// ---------------------------------------------------------------------------
// Device global scratch
// ---------------------------------------------------------------------------
__device__ float g_Eh[(size_t)V_ * R_];
__device__ float g_Et[(size_t)V_ * R_];
__device__ uint32_t g_Wf[(size_t)3 * 128 * 16384];
__device__ uint32_t g_Sf[2 * 32768];
__device__ float g_outb[(size_t)N_ * U_];
__device__ float g_logits[(size_t)N_ * S_];
__device__ float g_sbv[S_];
__device__ float g_loss[N_];
__device__ unsigned int g_bar;
// B fragment buffers: [K/16][N/8][lane32] uint4{hi0,hi1,lo0,lo1}
__device__ uint4 g_Bf_eh[131072];
__device__ uint4 g_Bf_et[131072];
__device__ uint4 g_Bf_op[131072];
__device__ uint4 g_Bf_lg[131072];
// A fragment planes (bf16 hi only): [M/16][K/16][lane32] uint4
__device__ uint4 g_Aemb_h[512000];
__device__ uint4 g_Ast_h[2097152];   // states fragments, emitted by recurrence
__device__ uint4 g_Aob_h[1048576];

// ---------------------------------------------------------------------------
// PTX helpers
// ---------------------------------------------------------------------------
__device__ __forceinline__ void mma_acc(float* d, const uint4& a, uint32_t b0, uint32_t b1) {
    asm volatile(
        "mma.sync.aligned.m16n8k16.row.col.f32.bf16.bf16.f32 "
        "{%0,%1,%2,%3},{%4,%5,%6,%7},{%8,%9},{%0,%1,%2,%3};"
        : "+f"(d[0]), "+f"(d[1]), "+f"(d[2]), "+f"(d[3])
        : "r"(a.x), "r"(a.y), "r"(a.z), "r"(a.w), "r"(b0), "r"(b1));
}
__device__ __forceinline__ uint4 ldg128cg(const uint4* p) {
    uint4 v;
    asm volatile("ld.global.cg.v4.u32 {%0,%1,%2,%3}, [%4];"
                 : "=r"(v.x), "=r"(v.y), "=r"(v.z), "=r"(v.w) : "l"(p));
    return v;
}
__device__ __forceinline__ float2 ldcg64f(const float* p) {
    float2 v;
    asm volatile("ld.global.cg.v2.f32 {%0,%1}, [%2];" : "=f"(v.x), "=f"(v.y) : "l"(p));
    return v;
}
__device__ __forceinline__ void grid_sync(unsigned int target, unsigned int* bar) {
    __syncthreads();
    if (threadIdx.x == 0) {
        asm volatile("red.release.gpu.global.add.u32 [%0], 1;" :: "l"(bar) : "memory");
        unsigned int v;
        do {
            asm volatile("ld.acquire.gpu.global.u32 %0, [%1];" : "=r"(v) : "l"(bar) : "memory");
        } while (v < target);
    }
    __syncthreads();
}
__device__ __forceinline__ uint32_t pack_hi(float x0, float x1) {
    uint16_t h0 = __bfloat16_as_ushort(__float2bfloat16(x0));
    uint16_t h1 = __bfloat16_as_ushort(__float2bfloat16(x1));
    return ((uint32_t)h1 << 16) | h0;
}
__device__ __forceinline__ uint32_t pack_lo(float x0, float x1) {
    float r0 = x0 - __bfloat162float(__float2bfloat16(x0));
    float r1 = x1 - __bfloat162float(__float2bfloat16(x1));
    return pack_hi(r0, r1);
}
__device__ __forceinline__ float tanh_ap(float x) {
    float y;
    asm("tanh.approx.f32 %0, %1;" : "=f"(y) : "f"(x));
    return y;
}
__device__ __forceinline__ float sigm_ap(float x) {
    float e;
    asm("ex2.approx.f32 %0, %1;" : "=f"(e) : "f"(-x * 1.4426950408889634f));
    float r;
    asm("rcp.approx.f32 %0, %1;" : "=f"(r) : "f"(1.f + e));
    return r;
}

// ---------------------------------------------------------------------------
// Setup kernels
// ---------------------------------------------------------------------------
__global__ void init_kernel(uint32_t* sf) {
    int i = blockIdx.x * 256 + threadIdx.x;
    if (i == 0) g_bar = 0u;
    if (i < 2 * 32768) sf[i] = 0u;
}

__global__ void sb_kernel(const int* __restrict__ sampled,
                          const float* __restrict__ softmax_b,
                          const float* __restrict__ scounts,
                          float* __restrict__ sbv) {
    int j = blockIdx.x * 256 + threadIdx.x;
    if (j < S_) sbv[j] = softmax_b[sampled[j]] - logf(scounts[j]);
}

// B-fragment prep from row-major src[k][n]
__global__ __launch_bounds__(256)
void prep_b_kn(const float* __restrict__ src, uint4* __restrict__ out,
               int K, int N, int ldb) {
    int idx = blockIdx.x * 256 + threadIdx.x;
    int total = (K >> 4) * (N >> 3) * 32;
    if (idx >= total) return;
    int lane = idx & 31;
    int nt = (idx >> 5) % (N >> 3);
    int gks = (idx >> 5) / (N >> 3);
    int g = lane >> 2, tg = lane & 3;
    int n = nt * 8 + g;
    int k0 = gks * 16 + tg * 2;
    float a0 = src[(size_t)k0 * ldb + n];
    float a1 = src[(size_t)(k0 + 1) * ldb + n];
    float a2 = src[(size_t)(k0 + 8) * ldb + n];
    float a3 = src[(size_t)(k0 + 9) * ldb + n];
    out[idx] = make_uint4(pack_hi(a0, a1), pack_hi(a2, a3),
                          pack_lo(a0, a1), pack_lo(a2, a3));
}

__global__ __launch_bounds__(256)
void prep_b_gather(const float* __restrict__ sw, const int* __restrict__ sampled,
                   uint4* __restrict__ out) {
    int idx = blockIdx.x * 256 + threadIdx.x;
    const int K = U_, N = S_;
    int total = (K >> 4) * (N >> 3) * 32;
    if (idx >= total) return;
    int lane = idx & 31;
    int nt = (idx >> 5) % (N >> 3);
    int gks = (idx >> 5) / (N >> 3);
    int g = lane >> 2, tg = lane & 3;
    int n = nt * 8 + g;
    int k0 = gks * 16 + tg * 2;
    const float* row = sw + (size_t)sampled[n] * U_;
    float a0 = row[k0], a1 = row[k0 + 1], a2 = row[k0 + 8], a3 = row[k0 + 9];
    out[idx] = make_uint4(pack_hi(a0, a1), pack_hi(a2, a3),
                          pack_lo(a0, a1), pack_lo(a2, a3));
}

// A-fragment prep (hi plane only), plain row-major source.
__global__ __launch_bounds__(256)
void prep_a0(const float* __restrict__ src, uint4* __restrict__ hi,
             int M, int K, int lda) {
    int idx = blockIdx.x * 256 + threadIdx.x;
    int total = (M >> 4) * (K >> 4) * 32;
    if (idx >= total) return;
    int lane = idx & 31;
    int kt = (idx >> 5) % (K >> 4);
    int mt = (idx >> 5) / (K >> 4);
    int r = lane >> 2;
    int k0 = kt * 16 + (lane & 3) * 2;
    int row0 = mt * 16 + r, row1 = row0 + 8;
    const float* p0 = src + (size_t)row0 * lda;
    const float* p1 = src + (size_t)row1 * lda;
    float2 v0 = *(const float2*)(p0 + k0);
    float2 v1 = *(const float2*)(p1 + k0);
    float2 v2 = *(const float2*)(p0 + k0 + 8);
    float2 v3 = *(const float2*)(p1 + k0 + 8);
    hi[idx] = make_uint4(pack_hi(v0.x, v0.y), pack_hi(v1.x, v1.y),
                         pack_hi(v2.x, v2.y), pack_hi(v3.x, v3.y));
}

// Weight -> fragment-linear bf16 hi/lo for recurrence (lo kept for layout
// compatibility; recurrence now reads hi only).
__global__ __launch_bounds__(256)
void wcvt_kernel(const float* __restrict__ Wh0, const float* __restrict__ Wt0,
                 const float* __restrict__ Wh,  const float* __restrict__ Wt,
                 uint32_t* __restrict__ Wf) {
    __shared__ float ws[256][17];
    int b = blockIdx.x;
    int cta = b & 127;
    int l = b >> 7;
    int cbase = cta * 8;
    int tid = threadIdx.x;
    uint32_t* outp = Wf + (size_t)(l * 128 + cta) * 16384;

    for (int kb = 0; kb < 4; kb++) {
#pragma unroll
        for (int e = 0; e < 16; e++) {
            int idx = tid + e * 256;
            int k = idx >> 4, cg = idx & 15;
            int g = cg >> 3, c = cg & 7;
            int kg = kb * 256 + k;
            float v;
            if (l == 0) v = (g ? Wt0 : Wh0)[(size_t)(U_ + kg) * R_ + cbase + c];
            else        v = (g ? Wt : Wh)[((size_t)(l - 1) * R_ + kg) * R_ + cbase + c];
            ws[k][g * 8 + c] = v;
        }
        __syncthreads();
#pragma unroll
        for (int e = 0; e < 16; e++) {
            int o = tid + e * 256;
            int ksl = o >> 8;
            int rem = o & 255;
            int term = rem >> 7;
            int rem2 = rem & 127;
            int lane = rem2 >> 2;
            int r = rem2 & 3;
            int gate = r & 1;
            int c = lane >> 2;
            int kk = (lane & 3) * 2 + (r >> 1) * 8;
            int kl = ksl * 16 + kk;
            float w0 = ws[kl][gate * 8 + c];
            float w1 = ws[kl + 1][gate * 8 + c];
            uint32_t val = term ? pack_lo(w0, w1) : pack_hi(w0, w1);
            int ks = kb * 16 + ksl;
            outp[((ks * 2 + term) * 32 + lane) * 4 + r] = val;
        }
        __syncthreads();
    }
}

// ---------------------------------------------------------------------------
// Fragment tensor GEMM (2-term: Ahi*(Bhi+Blo)). No smem, no syncs.
// ---------------------------------------------------------------------------
template <int EMITC>
__global__ __launch_bounds__(256)
void tgemm_f(const uint4* __restrict__ Ah, const uint4* __restrict__ Bf,
             const float* __restrict__ bias, float* __restrict__ C,
             uint4* __restrict__ Ch, int M, int N, int K, int ldc) {
    const int tid = threadIdx.x;
    const int lane = tid & 31;
    const int w = tid >> 5;
    const int mh = w >> 2;
    const int nq = w & 3;
    const int bm = blockIdx.y * 64;
    const int bn = blockIdx.x * 64;
    const int KT = K >> 4, NT = N >> 3;

    const int mt0 = (bm >> 4) + mh * 2;
    const uint4* A0h = Ah + ((size_t)mt0 * KT) * 32 + lane;
    const uint4* A1h = A0h + (size_t)KT * 32;
    const uint4* Bp0 = Bf + ((size_t)(bn >> 3) + nq * 2) * 32 + lane;

    float d[2][2][4];
#pragma unroll
    for (int i = 0; i < 2; i++)
#pragma unroll
        for (int j = 0; j < 2; j++)
#pragma unroll
            for (int q = 0; q < 4; q++) d[i][j][q] = 0.f;

#pragma unroll 4
    for (int kt = 0; kt < KT; kt++) {
        uint4 aH0 = __ldg(A0h + kt * 32);
        uint4 aH1 = __ldg(A1h + kt * 32);
        uint4 b0 = ldg128cg(Bp0 + (size_t)kt * NT * 32);
        uint4 b1 = ldg128cg(Bp0 + (size_t)kt * NT * 32 + 32);
        mma_acc(d[0][0], aH0, b0.x, b0.y);
        mma_acc(d[0][0], aH0, b0.z, b0.w);
        mma_acc(d[0][1], aH0, b1.x, b1.y);
        mma_acc(d[0][1], aH0, b1.z, b1.w);
        mma_acc(d[1][0], aH1, b0.x, b0.y);
        mma_acc(d[1][0], aH1, b0.z, b0.w);
        mma_acc(d[1][1], aH1, b1.x, b1.y);
        mma_acc(d[1][1], aH1, b1.z, b1.w);
    }

    const int g = lane >> 2, tg = lane & 3;
#pragma unroll
    for (int mti = 0; mti < 2; mti++) {
        int row0 = bm + (mh * 2 + mti) * 16 + g;
        float v[2][4];
#pragma unroll
        for (int nti = 0; nti < 2; nti++) {
            int col = bn + nq * 16 + nti * 8 + tg * 2;
            float b0v = bias ? bias[col] : 0.f;
            float b1v = bias ? bias[col + 1] : 0.f;
            v[nti][0] = d[mti][nti][0] + b0v;
            v[nti][1] = d[mti][nti][1] + b1v;
            v[nti][2] = d[mti][nti][2] + b0v;
            v[nti][3] = d[mti][nti][3] + b1v;
            C[(size_t)row0 * ldc + col]           = v[nti][0];
            C[(size_t)row0 * ldc + col + 1]       = v[nti][1];
            C[(size_t)(row0 + 8) * ldc + col]     = v[nti][2];
            C[(size_t)(row0 + 8) * ldc + col + 1] = v[nti][3];
        }
        if (EMITC) {
            int KT2 = N >> 4;
            int mtile = (bm >> 4) + mh * 2 + mti;
            int ktile = (bn >> 4) + nq;
            size_t fi = ((size_t)mtile * KT2 + ktile) * 32 + lane;
            Ch[fi] = make_uint4(pack_hi(v[0][0], v[0][1]), pack_hi(v[0][2], v[0][3]),
                                pack_hi(v[1][0], v[1][1]), pack_hi(v[1][2], v[1][3]));
        }
    }
}

// ---------------------------------------------------------------------------
// Persistent recurrence (8-warp K-split, smem partials, W-hi only MMA).
// Emits states A-fragments directly at l==2.
// ---------------------------------------------------------------------------
__global__ __launch_bounds__(RTHR, 1)
void rec_mma_kernel(const uint32_t* __restrict__ Wf,
                    uint32_t* __restrict__ Sf,
                    const int* __restrict__ input_data,
                    const float* __restrict__ Eh, const float* __restrict__ Et,
                    const float* __restrict__ bh, const float* __restrict__ bt,
                    uint32_t* __restrict__ AstF) {
    __shared__ float part[8][16][68];
    __shared__ float sold[64][9];
    __shared__ float bias_s[32];

    const int tid = threadIdx.x;
    const int lane = tid & 31;
    const int w = tid >> 5;
    const int cta = blockIdx.x;
    const int cbase = cta * 8;
    const int eb = tid & 63;
    const int ec0 = (tid >> 6) * 2;

    for (int i = tid; i < 64 * 9; i += RTHR) ((float*)sold)[i] = 0.f;
    if (tid < 32) {
        int l2 = tid >> 4, g = (tid >> 3) & 1, c = tid & 7;
        bias_s[tid] = (g ? bt : bh)[l2 * R_ + cbase + c];
    }
    __syncthreads();

    float2 pe_h, pe_t;
    {
        int vid = __ldg(&input_data[eb * T_ + 0]);
        pe_h = ldcg64f(&Eh[(size_t)vid * R_ + cbase + ec0]);
        pe_t = ldcg64f(&Et[(size_t)vid * R_ + cbase + ec0]);
    }

    // constant part of the Ast-fragment index: row = eb*T + t, k = cbase + ec0
    const int kglob = cbase + ec0;
    const int ktile = kglob >> 4;
    const int kk = kglob & 15;
    const int lane_k = (kk >> 1) & 3;
    const int comp_k = (kk & 8) ? 2 : 0;
    const int mt_base = eb * 16;

    unsigned int pc = 0;
    int t = 0, l = 0;

    for (int p = 0; p < 3 * T_; p++) {
        const int rbuf = p & 1;
        const uint4* SB = (const uint4*)(Sf + rbuf * 32768);
        uint32_t* sOut = Sf + (rbuf ^ 1) * 32768;
        const uint4* WA = (const uint4*)Wf + (size_t)(l * 128 + cta) * 4096;

        float dH[8][4];
#pragma unroll
        for (int g = 0; g < 8; g++)
#pragma unroll
            for (int q = 0; q < 4; q++) dH[g][q] = 0.f;

        const int ks0 = w * 8;
#pragma unroll 4
        for (int j = 0; j < 8; j++) {
            int ks = ks0 + j;
            uint4 aH = __ldg(WA + (ks * 2 + 0) * 32 + lane);
            uint4 bF[4];
#pragma unroll
            for (int gp = 0; gp < 4; gp++)
                bF[gp] = ldg128cg(SB + (ks * 4 + gp) * 32 + lane);
#pragma unroll
            for (int gp = 0; gp < 4; gp++) {
                mma_acc(dH[2 * gp],     aH, bF[gp].x, bF[gp].y);
                mma_acc(dH[2 * gp + 1], aH, bF[gp].z, bF[gp].w);
            }
        }

        {
            int row = lane >> 2;
            int nb = (lane & 3) * 2;
#pragma unroll
            for (int g = 0; g < 8; g++) {
                *(float2*)&part[w][row][nb + g * 8] =
                    make_float2(dH[g][0], dH[g][1]);
                *(float2*)&part[w][row + 8][nb + g * 8] =
                    make_float2(dH[g][2], dH[g][3]);
            }
        }
        __syncthreads();

        {
            uint16_t sh[2];
#pragma unroll
            for (int s = 0; s < 2; s++) {
                int c = ec0 + s;
                float zh = 0.f, zt = 0.f;
#pragma unroll
                for (int q = 0; q < 8; q++) {
                    zh += part[q][c][eb];
                    zt += part[q][8 + c][eb];
                }
                if (l == 0) {
                    zh += (s == 0) ? pe_h.x : pe_h.y;
                    zt += (s == 0) ? pe_t.x : pe_t.y;
                } else {
                    zh += bias_s[(l - 1) * 16 + c];
                    zt += bias_s[(l - 1) * 16 + 8 + c];
                }
                float so = sold[eb][c];
                float hh = tanh_ap(zh);
                float tg = sigm_ap(zt);
                float sn = (hh - so) * tg + so;
                sold[eb][c] = sn;
                sh[s] = __bfloat16_as_ushort(__float2bfloat16(sn));
            }
            uint32_t word = ((uint32_t)sh[1] << 16) | sh[0];

            // state fragment for next phase's MMA
            {
                int kk0 = (cta & 1) * 8 + ec0;
                int q = (kk0 >> 1) & 3;
                int reg = cta & 1;
                int g = eb >> 3;
                int lt = (eb & 7) * 4 + q;
                int ks = cta >> 1;
                int slot = (g & 1) * 2 + reg;
                int gp = g >> 1;
                sOut[(uint32_t)(((ks * 4 + gp) * 32 + lt) * 4 + slot)] = word;
            }

            // outproj A-fragment emission at l==2 (row = eb*T + t)
            if (l == 2) {
                int rin = t & 15;
                int mt = mt_base + (t >> 4);
                int lane2 = ((rin & 7) << 2) | lane_k;
                int comp = comp_k + ((rin & 8) ? 1 : 0);
                size_t fi = (((size_t)mt * 64 + ktile) * 32 + lane2) * 4 + comp;
                AstF[fi] = word;
            }
        }

        if (l == 1) {
            int tq = (t < T_ - 1) ? t + 1 : t;
            int vid = __ldg(&input_data[eb * T_ + tq]);
            pe_h = ldcg64f(&Eh[(size_t)vid * R_ + cbase + ec0]);
            pe_t = ldcg64f(&Et[(size_t)vid * R_ + cbase + ec0]);
        }

        pc++;
        grid_sync(RCTA * pc, &g_bar);
        if (++l == 3) { l = 0; t++; }
    }
}

// ---------------------------------------------------------------------------
// Loss (single-pass online softmax) + mean
// ---------------------------------------------------------------------------
__global__ __launch_bounds__(256)
void loss_kernel(const float* __restrict__ outb,
                 const float* __restrict__ logits,
                 const int* __restrict__ targets,
                 const int* __restrict__ sampled,
                 const float* __restrict__ true_counts,
                 const float* __restrict__ sw,
                 const float* __restrict__ softmax_b,
                 float* __restrict__ loss) {
    __shared__ float rm[256], rs[256];
    __shared__ float sh_true;
    const int i = blockIdx.x;
    const int tid = threadIdx.x;
    const int label = targets[i];

    float pdot = 0.f;
    for (int u = tid; u < U_; u += 256)
        pdot += outb[(size_t)i * U_ + u] * sw[(size_t)label * U_ + u];
    rm[tid] = pdot; __syncthreads();
    for (int s = 128; s > 0; s >>= 1) {
        if (tid < s) rm[tid] += rm[tid + s];
        __syncthreads();
    }
    if (tid == 0) sh_true = rm[0] + softmax_b[label] - logf(true_counts[i]);
    __syncthreads();
    const float tl = sh_true;

    float m = -1e30f, ssum = 0.f;
    for (int j = tid; j < S_; j += 256) {
        float v = logits[(size_t)i * S_ + j];
        if (sampled[j] == label) v -= 1e9f;
        if (v <= m) {
            ssum += __expf(v - m);
        } else {
            ssum = ssum * __expf(m - v) + 1.f;
            m = v;
        }
    }
    rm[tid] = m; rs[tid] = ssum;
    __syncthreads();
    for (int s = 128; s > 0; s >>= 1) {
        if (tid < s) {
            float m2 = rm[tid + s], s2 = rs[tid + s];
            float m1 = rm[tid], s1 = rs[tid];
            float nm = fmaxf(m1, m2);
            rs[tid] = s1 * __expf(m1 - nm) + s2 * __expf(m2 - nm);
            rm[tid] = nm;
        }
        __syncthreads();
    }
    if (tid == 0) {
        float m0 = rm[0], s0 = rs[0];
        float nm = fmaxf(m0, tl);
        float total = s0 * __expf(m0 - nm) + __expf(tl - nm);
        loss[i] = nm + logf(total) - tl;
    }
}

__global__ void reduce_mean_kernel(const float* __restrict__ loss, float* __restrict__ out) {
    __shared__ float red[256];
    const int tid = threadIdx.x;
    float s = 0.f;
    for (int i = tid; i < N_; i += 256) s += loss[i];
    red[tid] = s; __syncthreads();
    for (int st = 128; st > 0; st >>= 1) {
        if (tid < st) red[tid] += red[tid + st];
        __syncthreads();
    }
    if (tid == 0) out[0] = red[0] / (float)N_;
}

// ---------------------------------------------------------------------------
// Launch
// ---------------------------------------------------------------------------
extern "C" void kernel_launch(void* const* d_in, const int* in_sizes, int n_in,
                              void* d_out, int out_size) {
    const int*   input_data = (const int*)d_in[0];
    const int*   targets    = (const int*)d_in[1];
    const int*   sampled    = (const int*)d_in[2];
    const float* true_cnt   = (const float*)d_in[3];
    const float* samp_cnt   = (const float*)d_in[4];
    const float* embedding  = (const float*)d_in[5];
    const float* Wh0        = (const float*)d_in[6];
    const float* bh0        = (const float*)d_in[7];
    const float* Wt0        = (const float*)d_in[8];
    const float* bt0        = (const float*)d_in[9];
    const float* Wh         = (const float*)d_in[10];
    const float* bh         = (const float*)d_in[11];
    const float* Wt         = (const float*)d_in[12];
    const float* bt         = (const float*)d_in[13];
    const float* Wp         = (const float*)d_in[14];
    const float* bp         = (const float*)d_in[15];
    const float* sw         = (const float*)d_in[16];
    const float* smb        = (const float*)d_in[17];
    float* out = (float*)d_out;

    float *Eh, *Et, *outb, *logits, *sbv, *lossv;
    uint32_t *Wf, *Sf;
    uint4 *BfEh, *BfEt, *BfOp, *BfLg;
    uint4 *AembH, *AstH, *AobH;
    cudaGetSymbolAddress((void**)&Eh, g_Eh);
    cudaGetSymbolAddress((void**)&Et, g_Et);
    cudaGetSymbolAddress((void**)&outb, g_outb);
    cudaGetSymbolAddress((void**)&logits, g_logits);
    cudaGetSymbolAddress((void**)&sbv, g_sbv);
    cudaGetSymbolAddress((void**)&lossv, g_loss);
    cudaGetSymbolAddress((void**)&Wf, g_Wf);
    cudaGetSymbolAddress((void**)&Sf, g_Sf);
    cudaGetSymbolAddress((void**)&BfEh, g_Bf_eh);
    cudaGetSymbolAddress((void**)&BfEt, g_Bf_et);
    cudaGetSymbolAddress((void**)&BfOp, g_Bf_op);
    cudaGetSymbolAddress((void**)&BfLg, g_Bf_lg);
    cudaGetSymbolAddress((void**)&AembH, g_Aemb_h);
    cudaGetSymbolAddress((void**)&AstH, g_Ast_h);
    cudaGetSymbolAddress((void**)&AobH, g_Aob_h);

    init_kernel<<<(2 * 32768 + 255) / 256, 256>>>(Sf);
    sb_kernel<<<(S_ + 255) / 256, 256>>>(sampled, smb, samp_cnt, sbv);
    wcvt_kernel<<<384, 256>>>(Wh0, Wt0, Wh, Wt, Wf);

    // B fragment preps
    prep_b_kn<<<512, 256>>>(Wh0, BfEh, U_, R_, R_);
    prep_b_kn<<<512, 256>>>(Wt0, BfEt, U_, R_, R_);
    prep_b_kn<<<512, 256>>>(Wp, BfOp, R_, U_, U_);
    prep_b_gather<<<512, 256>>>(sw, sampled, BfLg);

    // A fragment prep: embedding
    prep_a0<<<2000, 256>>>(embedding, AembH, V_, U_, U_);

    // Vocab-space x-part precompute
    {
        dim3 grid(R_ / 64, V_ / 64);
        tgemm_f<0><<<grid, 256>>>(AembH, BfEh, bh0, Eh, nullptr, V_, R_, U_, R_);
        tgemm_f<0><<<grid, 256>>>(AembH, BfEt, bt0, Et, nullptr, V_, R_, U_, R_);
    }

    // Persistent recurrence — emits states A-fragments directly
    rec_mma_kernel<<<RCTA, RTHR>>>(Wf, Sf, input_data, Eh, Et, bh, bt,
                                   (uint32_t*)AstH);

    // outputs = states @ Wp + bp ; emits outb A-fragments
    {
        dim3 grid(U_ / 64, N_ / 64);
        tgemm_f<1><<<grid, 256>>>(AstH, BfOp, bp, outb, AobH, N_, U_, R_, U_);
    }
    // sampled logits = outb @ sw[sampled].T + sbv
    {
        dim3 grid(S_ / 64, N_ / 64);
        tgemm_f<0><<<grid, 256>>>(AobH, BfLg, sbv, logits, nullptr, N_, S_, U_, S_);
    }

    loss_kernel<<<N_, 256>>>(outb, logits, targets, sampled, true_cnt, sw, smb, lossv);
    reduce_mean_kernel<<<1, 256>>>(lossv, out);
}